// round 12
// baseline (speedup 1.0000x reference)
#include <cuda_runtime.h>
#include <math.h>

#define BB 128
#define TT 256
#define DD 256
#define NSTK 32
#define ZO 1e-6f

// scratch (no allocations allowed)
__device__ float d_gbuf[BB * TT];            // g gate per (b,t)
__device__ float d_pop[BB * TT];             // pop gate per (b,t)
__device__ float d_latch[BB * TT * DD];      // latch state after step t (33.5 MB)

__device__ __forceinline__ float eluf(float v) { return v > 0.f ? v : expm1f(v); }

// packed f32x2 FMA (SASS FFMA2 — ptxas won't auto-fuse; PTX-only path)
#define FMA_F32X2(d, a, b, c) \
    asm("fma.rn.f32x2 %0, %1, %2, %3;" : "=l"(d) : "l"(a), "l"(b), "l"(c))
#define PACK_F32X2(d, lo, hi) \
    asm("mov.b64 %0, {%1, %2};" : "=l"(d) : "r"(__float_as_uint(lo)), "r"(__float_as_uint(hi)))
#define UNPACK_F32X2(lo, hi, v) \
    { unsigned int _l, _h; asm("mov.b64 {%0, %1}, %2;" : "=r"(_l), "=r"(_h) : "l"(v)); \
      lo = __uint_as_float(_l); hi = __uint_as_float(_h); }

// ---------------------------------------------------------------------------
// Pass 1: g[b,t] = elu(cos(latch_enable, x[b,t])) — one warp per (b,t) row.
// ---------------------------------------------------------------------------
__global__ void gpass_kernel(const float* __restrict__ x, const float* __restrict__ le) {
    int warp = (blockIdx.x * blockDim.x + threadIdx.x) >> 5;
    int lane = threadIdx.x & 31;
    if (warp >= BB * TT) return;
    const float4* xr = (const float4*)(x + (size_t)warp * DD);
    const float4* lr = (const float4*)le;
    float h1 = 0.f, h2 = 0.f, h0 = 0.f;
#pragma unroll
    for (int i = 0; i < 2; i++) {
        float4 xv = xr[lane * 2 + i];
        float4 lv = lr[lane * 2 + i];
        h1 += xv.x * lv.x + xv.y * lv.y + xv.z * lv.z + xv.w * lv.w;
        h2 += xv.x * xv.x + xv.y * xv.y + xv.z * xv.z + xv.w * xv.w;
        h0 += lv.x * lv.x + lv.y * lv.y + lv.z * lv.z + lv.w * lv.w;
    }
#pragma unroll
    for (int o = 16; o; o >>= 1) {
        h1 += __shfl_xor_sync(0xffffffffu, h1, o);
        h2 += __shfl_xor_sync(0xffffffffu, h2, o);
        h0 += __shfl_xor_sync(0xffffffffu, h0, o);
    }
    if (lane == 0) {
        float an = fmaxf(sqrtf(h0), 1e-8f);
        float bn = fmaxf(sqrtf(h2), 1e-8f);
        d_gbuf[warp] = eluf(h1 / (an * bn));
    }
}

// ---------------------------------------------------------------------------
// Pass 2: latch scan. One thread per (b,d); 256 serial FMAs.
// ---------------------------------------------------------------------------
__global__ void latch_scan_kernel(const float* __restrict__ x,
                                  const float* __restrict__ latch_init) {
    int idx = blockIdx.x * blockDim.x + threadIdx.x;   // = b*DD + d
    int b = idx >> 8;
    int d = idx & 255;
    float latch = latch_init[idx];
    const float* xp = x + (size_t)b * TT * DD + d;
    float* lp = d_latch + (size_t)b * TT * DD + d;
    const float* gp = d_gbuf + b * TT;
#pragma unroll 4
    for (int t = 0; t < TT; t++) {
        float g = gp[t];
        latch = fmaf(g, xp[(size_t)t * DD], (1.f - g) * latch);
        lp[(size_t)t * DD] = latch;
    }
}

// ---------------------------------------------------------------------------
// Pass 3: pop[b,t] = elu(cos(should_pop, latch_{t-1})); latch_{-1}=latch_init.
// ---------------------------------------------------------------------------
__global__ void pop_kernel(const float* __restrict__ sp,
                           const float* __restrict__ latch_init) {
    int warp = (blockIdx.x * blockDim.x + threadIdx.x) >> 5;
    int lane = threadIdx.x & 31;
    if (warp >= BB * TT) return;
    int b = warp >> 8;
    int t = warp & 255;
    const float4* lr = (t == 0)
        ? (const float4*)(latch_init + (size_t)b * DD)
        : (const float4*)(d_latch + ((size_t)b * TT + (t - 1)) * DD);
    const float4* sr = (const float4*)sp;
    float h1 = 0.f, h2 = 0.f, h0 = 0.f;
#pragma unroll
    for (int i = 0; i < 2; i++) {
        float4 lv = lr[lane * 2 + i];
        float4 sv = sr[lane * 2 + i];
        h1 += lv.x * sv.x + lv.y * sv.y + lv.z * sv.z + lv.w * sv.w;
        h2 += lv.x * lv.x + lv.y * lv.y + lv.z * lv.z + lv.w * lv.w;
        h0 += sv.x * sv.x + sv.y * sv.y + sv.z * sv.z + sv.w * sv.w;
    }
#pragma unroll
    for (int o = 16; o; o >>= 1) {
        h1 += __shfl_xor_sync(0xffffffffu, h1, o);
        h2 += __shfl_xor_sync(0xffffffffu, h2, o);
        h0 += __shfl_xor_sync(0xffffffffu, h0, o);
    }
    if (lane == 0) {
        float an = fmaxf(sqrtf(h0), 1e-8f);
        float bn = fmaxf(sqrtf(h2), 1e-8f);
        d_pop[warp] = eluf(h1 / (an * bn));
    }
}

// ---------------------------------------------------------------------------
// Pass 4: main scan. One CTA per batch; 8 autonomous warps (32 cols each).
// Pointer chain SOFTWARE-PIPELINED one step ahead: iteration t consumes
// coef_t (smem, written last iteration) while computing coef_{t+1}; the
// chain's shfl/MUFU latency is interleaved with packed-FFMA2 stack chunks.
// Stack pairs 2 slots per 64-bit reg: per 2 slots = 2 LDS.128 + 3 FFMA2.
// ---------------------------------------------------------------------------
__global__ void __launch_bounds__(DD, 1) stack_main_kernel(
    const float* __restrict__ x,
    const float* __restrict__ shp,
    float* __restrict__ out)
{
    // [warp][buf][pair i]: s_ca = {c0,c1,a0,a1}, s_ep = {e0,e1,pw0,pw1}
    __shared__ float4 s_ca[8][2][NSTK / 2];
    __shared__ float4 s_ep[8][2][NSTK / 2];
    __shared__ float  s_pop[TT + 1];

    const int b = blockIdx.x;
    const int tid = threadIdx.x;
    const int wid = tid >> 5, lane = tid & 31;

    s_pop[tid] = d_pop[b * TT + tid];
    if (tid == 0) s_pop[TT] = 0.f;         // read by last iter's dead chain
    __syncthreads();

    const float sharpen = shp[0];
    float ptr = (lane == 0) ? 1.f : ZO;    // raw initial pointer (matches ref)

    unsigned long long st2[NSTK / 2];      // packed stack pairs {st[2i],st[2i+1]}
    unsigned long long zz; PACK_F32X2(zz, ZO, ZO);
#pragma unroll
    for (int i = 0; i < NSTK / 2; i++) st2[i] = zz;

    const float* xb = x + (size_t)b * TT * DD + tid;
    float* ob = out + (size_t)b * TT * DD + tid;

    // scalar STS offsets for this lane (pair layout)
    float* wca = (float*)&s_ca[wid][0][0] + (lane >> 1) * 4 + (lane & 1);
    float* wep = (float*)&s_ep[wid][0][0] + (lane >> 1) * 4 + (lane & 1);
    const int bufstride = (NSTK / 2) * 4;  // floats per buf

    // ---- prologue: chain for t=0 into buf 0 ----
    {
        float pop = s_pop[0];
        float push = 1.f - pop;
        float pp = __shfl_sync(0xffffffffu, ptr, (lane + 31) & 31);
        float pq = __shfl_sync(0xffffffffu, ptr, (lane + 1) & 31);
        float a  = push * pp;
        float bb = pop * ptr;
        float c  = 1.f - a - bb;
        float e  = ZO * bb;
        float np = a + pop * pq;
        float q  = __powf(fmaxf(fmaxf(np, 0.f), 1e-12f), sharpen);
        float qs = q;
#pragma unroll
        for (int o = 16; o; o >>= 1) qs += __shfl_xor_sync(0xffffffffu, qs, o);
        float pn = __fdividef(q, fmaxf(qs, 1e-8f));
        wca[0] = c; wca[2] = a;
        wep[0] = e; wep[2] = pop * pn;
        ptr = pn;
        __syncwarp();
    }

    float xv = xb[0];
    int par = 0;
    for (int t = 0; t < TT; t++) {
        int tn = (t + 1 < TT) ? t + 1 : t;
        float xnext = xb[(size_t)tn * DD];

        unsigned long long xx; PACK_F32X2(xx, xv, xv);
        unsigned long long acc; PACK_F32X2(acc, 0.f, 0.f);
        const ulonglong2* ca = (const ulonglong2*)&s_ca[wid][par][0];
        const ulonglong2* ep = (const ulonglong2*)&s_ep[wid][par][0];

        // ---- chain for t+1, interleaved with stack chunks using coef_t ----
        float pop1 = s_pop[t + 1];
        float push1 = 1.f - pop1;
        float pp = __shfl_sync(0xffffffffu, ptr, (lane + 31) & 31);
        float pq = __shfl_sync(0xffffffffu, ptr, (lane + 1) & 31);

#pragma unroll
        for (int i = 0; i < 4; i++) {   // slots 0..7
            ulonglong2 k1 = ca[i]; ulonglong2 k2 = ep[i];
            unsigned long long f;
            FMA_F32X2(f, k1.y, xx, k2.x);
            FMA_F32X2(st2[i], k1.x, st2[i], f);
            FMA_F32X2(acc, k2.y, st2[i], acc);
        }

        float a1  = push1 * pp;
        float bb1 = pop1 * ptr;
        float c1  = 1.f - a1 - bb1;
        float e1  = ZO * bb1;
        float np  = a1 + pop1 * pq;
        float q   = __powf(fmaxf(fmaxf(np, 0.f), 1e-12f), sharpen);

#pragma unroll
        for (int i = 4; i < 8; i++) {   // slots 8..15
            ulonglong2 k1 = ca[i]; ulonglong2 k2 = ep[i];
            unsigned long long f;
            FMA_F32X2(f, k1.y, xx, k2.x);
            FMA_F32X2(st2[i], k1.x, st2[i], f);
            FMA_F32X2(acc, k2.y, st2[i], acc);
        }

        float qs = q;
        qs += __shfl_xor_sync(0xffffffffu, qs, 16);
        qs += __shfl_xor_sync(0xffffffffu, qs, 8);

#pragma unroll
        for (int i = 8; i < 12; i++) {  // slots 16..23
            ulonglong2 k1 = ca[i]; ulonglong2 k2 = ep[i];
            unsigned long long f;
            FMA_F32X2(f, k1.y, xx, k2.x);
            FMA_F32X2(st2[i], k1.x, st2[i], f);
            FMA_F32X2(acc, k2.y, st2[i], acc);
        }

        qs += __shfl_xor_sync(0xffffffffu, qs, 4);
        qs += __shfl_xor_sync(0xffffffffu, qs, 2);
        qs += __shfl_xor_sync(0xffffffffu, qs, 1);
        float pn = __fdividef(q, fmaxf(qs, 1e-8f));

#pragma unroll
        for (int i = 12; i < 16; i++) { // slots 24..31
            ulonglong2 k1 = ca[i]; ulonglong2 k2 = ep[i];
            unsigned long long f;
            FMA_F32X2(f, k1.y, xx, k2.x);
            FMA_F32X2(st2[i], k1.x, st2[i], f);
            FMA_F32X2(acc, k2.y, st2[i], acc);
        }

        float alo, ahi; UNPACK_F32X2(alo, ahi, acc);
        ob[(size_t)t * DD] = alo + ahi;

        // publish coef_{t+1} into the other buffer
        int nb = par ^ 1;
        wca[nb * bufstride] = c1; wca[nb * bufstride + 2] = a1;
        wep[nb * bufstride] = e1; wep[nb * bufstride + 2] = pop1 * pn;
        ptr = pn;
        __syncwarp();

        xv = xnext;
        par = nb;
    }
}

// ---------------------------------------------------------------------------
extern "C" void kernel_launch(void* const* d_in, const int* in_sizes, int n_in,
                              void* d_out, int out_size) {
    const float* x   = (const float*)d_in[0];  // [128,256,256]
    const float* sp  = (const float*)d_in[1];  // [256]
    const float* shp = (const float*)d_in[2];  // [1]
    const float* le  = (const float*)d_in[3];  // [256]
    const float* li  = (const float*)d_in[4];  // [128,256]
    float* out = (float*)d_out;                // [128,256,256]

    gpass_kernel<<<(BB * TT) / 8, 256>>>(x, le);
    latch_scan_kernel<<<(BB * DD) / 256, 256>>>(x, li);
    pop_kernel<<<(BB * TT) / 8, 256>>>(sp, li);
    stack_main_kernel<<<BB, DD>>>(x, shp, out);
}